// round 8
// baseline (speedup 1.0000x reference)
#include <cuda_runtime.h>
#include <cuda_bf16.h>
#include <cstdint>

#define B_  8
#define C_  256
#define N_  2048
#define D_  32
#define BJ  64
#define NT  (N_ / BJ)
#define LOG2E 1.4426950408889634f

// ---------------------------------------------------------------------------
// Device-global scratch (allocation-free)
// ---------------------------------------------------------------------------
__device__ __nv_bfloat16  g_xt [(size_t)B_ * N_ * C_];   // x^T  (B,N,C) bf16
__device__ __nv_bfloat16  g_qt [(size_t)B_ * N_ * D_];   // q^T  (B,N,D) bf16, scaled by log2e
__device__ __nv_bfloat16  g_kt [(size_t)B_ * N_ * D_];   // k^T  (B,N,D) bf16
__device__ __nv_bfloat16  g_vbf[(size_t)B_ * C_ * N_];   // v    (B,C,N) bf16
__device__ __nv_bfloat16  g_wvbf[C_ * C_];               // wv bf16

// ---------------------------------------------------------------------------
// PTX helpers (legacy mma path: compute_100 PTX target, no tcgen05)
// ---------------------------------------------------------------------------
__device__ __forceinline__ uint32_t smem_u32(const void* p) {
    uint32_t a;
    asm("{ .reg .u64 t; cvta.to.shared.u64 t, %1; cvt.u32.u64 %0, t; }"
        : "=r"(a) : "l"(p));
    return a;
}
__device__ __forceinline__ void ldm_x4(uint32_t* r, uint32_t addr) {
    asm volatile("ldmatrix.sync.aligned.m8n8.x4.shared.b16 {%0,%1,%2,%3}, [%4];\n"
        : "=r"(r[0]), "=r"(r[1]), "=r"(r[2]), "=r"(r[3]) : "r"(addr));
}
__device__ __forceinline__ void mma_bf16(float* d, const uint32_t* a, const uint32_t* b) {
    asm volatile(
        "mma.sync.aligned.m16n8k16.row.col.f32.bf16.bf16.f32 "
        "{%0,%1,%2,%3},{%4,%5,%6,%7},{%8,%9},{%0,%1,%2,%3};\n"
        : "+f"(d[0]), "+f"(d[1]), "+f"(d[2]), "+f"(d[3])
        : "r"(a[0]), "r"(a[1]), "r"(a[2]), "r"(a[3]), "r"(b[0]), "r"(b[1]));
}
__device__ __forceinline__ uint32_t packbf2(float a, float b) {
    __nv_bfloat162 h = __floats2bfloat162_rn(a, b);
    return *(uint32_t*)&h;
}
__device__ __forceinline__ float ex2(float x) {
    float y;
    asm("ex2.approx.f32 %0, %1;" : "=f"(y) : "f"(x));
    return y;
}
#define CP_ASYNC16(saddr, gptr) \
    asm volatile("cp.async.cg.shared.global [%0], [%1], 16;\n" :: "r"(saddr), "l"(gptr))
#define CP_COMMIT() asm volatile("cp.async.commit_group;\n")
#define CP_WAIT0()  asm volatile("cp.async.wait_group 0;\n")
#define CP_WAIT1()  asm volatile("cp.async.wait_group 1;\n")
#define BAR_SYNC(id, cnt) \
    asm volatile("bar.sync %0, %1;" :: "r"(id), "r"(cnt) : "memory")

#define SMS 40   // 32 data + 8 pad bf16
#define VMS 72   // 64 data + 8 pad bf16

// Dispatch ranges for prep_kernel (FIX: pack_x needs 4096 blocks, not 1024)
#define PREP_PACKX  4096                      // 64 n-tiles x 8 c-tiles x 8 b
#define PREP_PACKW  (PREP_PACKX + 64)         // 4160
#define PREP_TOTAL  (PREP_PACKW + 256)        // 4416 (32 n-tiles x 8 b projqk)

// legacy 64x32 warp-tile step (projv mainloop)
__device__ __forceinline__ void mma_tile_step(
    uint32_t sA, uint32_t sB, int kk, int lane, int wm, int wn, float acc[4][4][4])
{
    const int rrow  = lane & 15;
    const int chalf = (lane >> 4) << 3;
    uint32_t a[4][4], bq[2][4];
    #pragma unroll
    for (int mt = 0; mt < 4; mt++)
        ldm_x4(a[mt], sA + (uint32_t)(((wm * 64 + mt * 16 + rrow) * SMS + kk + chalf) * 2));
    #pragma unroll
    for (int np = 0; np < 2; np++)
        ldm_x4(bq[np], sB + (uint32_t)(((wn * 32 + np * 16 + rrow) * SMS + kk + chalf) * 2));
    #pragma unroll
    for (int mt = 0; mt < 4; mt++)
        #pragma unroll
        for (int nt = 0; nt < 4; nt++) {
            uint32_t bb[2] = { bq[nt >> 1][nt & 1], bq[nt >> 1][(nt & 1) + 2] };
            mma_bf16(acc[mt][nt], a[mt], bb);
        }
}

// ---------------------------------------------------------------------------
// prep_kernel: block-dispatched fusion of
//   [0, 4096)        pack_x  : x (B,C,N) fp32 -> x^T (B,N,C) bf16
//   [4096, 4160)     pack_w  : wv fp32 -> bf16
//   [4160, 4416)     projqk  : q/k projection, q scaled by log2e
// ---------------------------------------------------------------------------
__global__ __launch_bounds__(256) void prep_kernel(
    const float* __restrict__ x,
    const float* __restrict__ wq, const float* __restrict__ bq,
    const float* __restrict__ wk, const float* __restrict__ bk,
    const float* __restrict__ wv,
    __nv_bfloat16* __restrict__ xt, __nv_bfloat16* __restrict__ wvb,
    __nv_bfloat16* __restrict__ qt, __nv_bfloat16* __restrict__ kt)
{
    __shared__ __align__(16) float sh[32 * 64 * 2];   // 16KB, overlaid
    const int bid = blockIdx.x, tid = threadIdx.x;

    if (bid < PREP_PACKX) {
        // ---- pack_x: tile (n0, c0, b) : 64 x 8 x 8 = 4096 blocks ----
        float (*t)[33] = (float(*)[33])sh;
        const int n0 = (bid & 63) * 32, c0 = ((bid >> 6) & 7) * 32, b = bid >> 9;
        #pragma unroll
        for (int r = 0; r < 4; r++) {
            const int c = (tid >> 5) + r * 8;
            t[c][tid & 31] = x[((size_t)b * C_ + c0 + c) * N_ + n0 + (tid & 31)];
        }
        __syncthreads();
        #pragma unroll
        for (int r = 0; r < 4; r++) {
            const int n = (tid >> 5) + r * 8;
            xt[((size_t)b * N_ + n0 + n) * C_ + c0 + (tid & 31)] =
                __float2bfloat16(t[tid & 31][n]);
        }
        return;
    }
    if (bid < PREP_PACKW) {
        // ---- pack_w: 64 blocks x 256 thr x 4 elems ----
        const int base = (bid - PREP_PACKX) * 1024 + tid * 4;
        const float4 w4 = *(const float4*)(wv + base);
        *(__nv_bfloat162*)(wvb + base)     = __floats2bfloat162_rn(w4.x, w4.y);
        *(__nv_bfloat162*)(wvb + base + 2) = __floats2bfloat162_rn(w4.z, w4.w);
        return;
    }

    // ---- projqk: 256 blocks = 32 n-tiles x 8 batches ----
    float (*Ws)[64] = (float(*)[64])sh;            // [kk][m]
    float (*Xs)[64] = (float(*)[64])(sh + 32 * 64);
    const int pid = bid - PREP_PACKW;
    const int n0 = (pid & 31) * 64, b = pid >> 5;
    const int tr = tid >> 4, tc = tid & 15;
    const float* xb = x + (size_t)b * C_ * N_;

    float acc[4][4] = {};
    for (int c0 = 0; c0 < C_; c0 += 32) {
        {
            const int m = tid >> 2;
            const float* wrow = (m < 32) ? (wq + (size_t)m * C_)
                                         : (wk + (size_t)(m - 32) * C_);
            #pragma unroll
            for (int h = 0; h < 2; h++) {
                const int k4 = (tid & 3) * 4 + h * 16;
                const float4 w4 = *(const float4*)(wrow + c0 + k4);
                Ws[k4 + 0][m] = w4.x; Ws[k4 + 1][m] = w4.y;
                Ws[k4 + 2][m] = w4.z; Ws[k4 + 3][m] = w4.w;
            }
        }
        {
            const int kk = tid >> 3, nn = (tid & 7) * 8;
            *(float4*)&Xs[kk][nn] =
                *(const float4*)(xb + (size_t)(c0 + kk) * N_ + n0 + nn);
            *(float4*)&Xs[kk][nn + 4] =
                *(const float4*)(xb + (size_t)(c0 + kk) * N_ + n0 + nn + 4);
        }
        __syncthreads();
        #pragma unroll
        for (int kk = 0; kk < 32; kk++) {
            const float4 wf = *(const float4*)&Ws[kk][tr * 4];
            const float4 xf = *(const float4*)&Xs[kk][tc * 4];
            acc[0][0] += wf.x * xf.x; acc[0][1] += wf.x * xf.y; acc[0][2] += wf.x * xf.z; acc[0][3] += wf.x * xf.w;
            acc[1][0] += wf.y * xf.x; acc[1][1] += wf.y * xf.y; acc[1][2] += wf.y * xf.z; acc[1][3] += wf.y * xf.w;
            acc[2][0] += wf.z * xf.x; acc[2][1] += wf.z * xf.y; acc[2][2] += wf.z * xf.z; acc[2][3] += wf.z * xf.w;
            acc[3][0] += wf.w * xf.x; acc[3][1] += wf.w * xf.y; acc[3][2] += wf.w * xf.z; acc[3][3] += wf.w * xf.w;
        }
        __syncthreads();
    }

    const int mbase = tr * 4;
    const bool isq = (mbase < 32);
    __nv_bfloat16* dst = isq ? qt : kt;
    const float* bias = isq ? bq : bk;
    const int mo = isq ? mbase : (mbase - 32);
    const float scl = isq ? LOG2E : 1.0f;   // fold log2(e) into q
    const float b0v = bias[mo], b1v = bias[mo + 1], b2v = bias[mo + 2], b3v = bias[mo + 3];
    #pragma unroll
    for (int j = 0; j < 4; j++) {
        const int n = n0 + tc * 4 + j;
        __nv_bfloat16* o = dst + ((size_t)b * N_ + n) * D_ + mo;
        *(__nv_bfloat162*)(o)     = __floats2bfloat162_rn((acc[0][j] + b0v) * scl,
                                                          (acc[1][j] + b1v) * scl);
        *(__nv_bfloat162*)(o + 2) = __floats2bfloat162_rn((acc[2][j] + b2v) * scl,
                                                          (acc[3][j] + b3v) * scl);
    }
}

// ---------------------------------------------------------------------------
// v projection (tensor core)
// ---------------------------------------------------------------------------
__global__ __launch_bounds__(256) void projv_tc(
    const __nv_bfloat16* __restrict__ wv, const float* __restrict__ bv,
    const __nv_bfloat16* __restrict__ xt, __nv_bfloat16* __restrict__ v)
{
    __shared__ __align__(16) __nv_bfloat16 sm[4 * 128 * SMS];
    const int b = blockIdx.z, m0 = blockIdx.y * 128, n0 = blockIdx.x * 128;
    const int tid = threadIdx.x, lane = tid & 31, warp = tid >> 5;
    const int wm = warp & 1, wn = warp >> 1;
    const uint32_t sbase = smem_u32(sm);
    const int row = tid >> 2, c8 = (tid & 3) << 3;

    const __nv_bfloat16* A = wv + (size_t)(m0 + row) * C_ + c8;
    const __nv_bfloat16* Bm = xt + ((size_t)b * N_ + n0 + row) * C_ + c8;

    float acc[4][4][4] = {};
    {
        const uint32_t sa = sbase + (uint32_t)((row * SMS + c8) * 2);
        CP_ASYNC16(sa,                        A);
        CP_ASYNC16(sa + 64 * SMS * 2,         A + (size_t)64 * C_);
        CP_ASYNC16(sa + 128 * SMS * 2,        Bm);
        CP_ASYNC16(sa + (128 + 64) * SMS * 2, Bm + (size_t)64 * C_);
        CP_COMMIT();
    }
    #pragma unroll 1
    for (int it = 0; it < 8; it++) {
        CP_WAIT0(); __syncthreads();
        if (it < 7) {
            const int st = (it + 1) & 1, j0 = (it + 1) * 32;
            const uint32_t sa = sbase + (uint32_t)(st * 2 * 128 * SMS * 2 + (row * SMS + c8) * 2);
            CP_ASYNC16(sa,                        A + j0);
            CP_ASYNC16(sa + 64 * SMS * 2,         A + j0 + (size_t)64 * C_);
            CP_ASYNC16(sa + 128 * SMS * 2,        Bm + j0);
            CP_ASYNC16(sa + (128 + 64) * SMS * 2, Bm + j0 + (size_t)64 * C_);
            CP_COMMIT();
        }
        const uint32_t sA = sbase + (uint32_t)((it & 1) * 2 * 128 * SMS * 2);
        const uint32_t sB = sA + 128 * SMS * 2;
        mma_tile_step(sA, sB, 0,  lane, wm, wn, acc);
        mma_tile_step(sA, sB, 16, lane, wm, wn, acc);
        __syncthreads();
    }
    #pragma unroll
    for (int mt = 0; mt < 4; mt++)
        #pragma unroll
        for (int h = 0; h < 2; h++) {
            const int m = m0 + wm * 64 + mt * 16 + (lane >> 2) + h * 8;
            const float bm = bv[m];
            #pragma unroll
            for (int nt = 0; nt < 4; nt++) {
                const int n = n0 + wn * 32 + nt * 8 + ((lane & 3) << 1);
                __nv_bfloat162 o;
                o.x = __float2bfloat16(acc[mt][nt][h * 2 + 0] + bm);
                o.y = __float2bfloat16(acc[mt][nt][h * 2 + 1] + bm);
                *(__nv_bfloat162*)(v + ((size_t)b * C_ + m) * N_ + n) = o;
            }
        }
}

// ---------------------------------------------------------------------------
// Flash attention (base-2 softmax, no max; q pre-scaled by log2e).
// Block = 64 i-rows x 128 c, 8 warps = 4 i-slices x 2 halves.
// ---------------------------------------------------------------------------
#define KOFF_B  (64 * SMS * 2)                       // 5120
#define VOFF_B  (KOFF_B + 3 * 64 * SMS * 2)          // 20480
#define POFF_B  (VOFF_B + 3 * 128 * VMS * 2)         // 75776
#define PPITCH  (16 * VMS * 2)                       // 2304 bytes per pair tile
#define FL_SMEM (POFF_B + 4 * PPITCH)                // 84992

__global__ __launch_bounds__(256, 2) void flash_tc(
    const __nv_bfloat16* __restrict__ qt, const __nv_bfloat16* __restrict__ kt,
    const __nv_bfloat16* __restrict__ v, const float* __restrict__ x,
    const float* __restrict__ gamma, float* __restrict__ out)
{
    extern __shared__ __align__(16) char smem_raw[];
    __shared__ float l_sm[2][64];

    const int b  = blockIdx.z;
    const int i0 = blockIdx.y * 64;
    const int c0 = blockIdx.x * 128;
    const int tid = threadIdx.x, lane = tid & 31, warp = tid >> 5;
    const int islice = warp >> 1;
    const int half   = warp & 1;
    const int rrow = lane & 15, chalf = (lane >> 4) << 3;

    const __nv_bfloat16* Qg = qt + ((size_t)b * N_ + i0) * D_;
    const __nv_bfloat16* Kg = kt + (size_t)b * N_ * D_;
    const __nv_bfloat16* Vg = v  + ((size_t)b * C_ + c0) * N_;

    const uint32_t sQa = smem_u32(smem_raw);
    const uint32_t sKa = sQa + KOFF_B;
    const uint32_t sVa = sQa + VOFF_B;
    const uint32_t sPa = sQa + POFF_B + (uint32_t)islice * PPITCH;

    // prologue: group0 = {Q, K0, V0}, group1 = {K1, V1}
    {
        const int r = tid >> 2, s = (tid & 3) * 8;
        CP_ASYNC16(sQa + (uint32_t)((r * SMS + s) * 2), Qg + (size_t)r * D_ + s);
        CP_ASYNC16(sKa + (uint32_t)((r * SMS + s) * 2), Kg + (size_t)r * D_ + s);
        #pragma unroll
        for (int p = 0; p < 4; p++) {
            const int idx = tid + p * 256, vr = idx >> 3, vs = (idx & 7) * 8;
            CP_ASYNC16(sVa + (uint32_t)((vr * VMS + vs) * 2), Vg + (size_t)vr * N_ + vs);
        }
        CP_COMMIT();
        CP_ASYNC16(sKa + (uint32_t)((64 * SMS + r * SMS + s) * 2),
                   Kg + (size_t)(BJ + r) * D_ + s);
        #pragma unroll
        for (int p = 0; p < 4; p++) {
            const int idx = tid + p * 256, vr = idx >> 3, vs = (idx & 7) * 8;
            CP_ASYNC16(sVa + (uint32_t)((128 * VMS + vr * VMS + vs) * 2),
                       Vg + (size_t)vr * N_ + BJ + vs);
        }
        CP_COMMIT();
    }

    float accO[8][4] = {};
    float l0 = 0.f, l1 = 0.f;
    uint32_t qf[2][4];

    #pragma unroll 1
    for (int t = 0; t < NT; t++) {
        CP_WAIT1(); __syncthreads();
        if (t == 0) {
            ldm_x4(qf[0], sQa + (uint32_t)(((islice * 16 + rrow) * SMS + 0  + chalf) * 2));
            ldm_x4(qf[1], sQa + (uint32_t)(((islice * 16 + rrow) * SMS + 16 + chalf) * 2));
        }
        if (t + 2 < NT) {
            const int bf = (t + 2) % 3, j1 = (t + 2) * BJ;
            const int r = tid >> 2, s = (tid & 3) * 8;
            CP_ASYNC16(sKa + (uint32_t)((bf * 64 * SMS + r * SMS + s) * 2),
                       Kg + (size_t)(j1 + r) * D_ + s);
            #pragma unroll
            for (int p = 0; p < 4; p++) {
                const int idx = tid + p * 256, vr = idx >> 3, vs = (idx & 7) * 8;
                CP_ASYNC16(sVa + (uint32_t)((bf * 128 * VMS + vr * VMS + vs) * 2),
                           Vg + (size_t)vr * N_ + j1 + vs);
            }
        }
        CP_COMMIT();

        const uint32_t kb = sKa + (uint32_t)((t % 3) * 64 * SMS * 2);
        const uint32_t vb = sVa + (uint32_t)((t % 3) * 128 * VMS * 2);

        // ---- S = Q K^T : warp computes 16i x 32j (its j-half) ----
        float accS[4][4] = {};
        #pragma unroll
        for (int jt2 = 0; jt2 < 2; jt2++) {
            const int jt = half * 2 + jt2;
            uint32_t b0[4], b1[4];
            ldm_x4(b0, kb + (uint32_t)(((jt * 16 + rrow) * SMS + 0  + chalf) * 2));
            ldm_x4(b1, kb + (uint32_t)(((jt * 16 + rrow) * SMS + 16 + chalf) * 2));
            #pragma unroll
            for (int np = 0; np < 2; np++) {
                uint32_t bb0[2] = { b0[np], b0[np + 2] };
                uint32_t bb1[2] = { b1[np], b1[np + 2] };
                mma_bf16(accS[jt2 * 2 + np], qf[0], bb0);
                mma_bf16(accS[jt2 * 2 + np], qf[1], bb1);
            }
        }

        // ---- 2^S (q carries log2e) + store P half + partial l ----
        #pragma unroll
        for (int t4 = 0; t4 < 4; t4++) {
            const float e0 = ex2(accS[t4][0]);
            const float e1 = ex2(accS[t4][1]);
            const float e2 = ex2(accS[t4][2]);
            const float e3 = ex2(accS[t4][3]);
            l0 += e0 + e1; l1 += e2 + e3;
            const int jcol = half * 32 + t4 * 8 + (lane & 3) * 2;
            const int r0 = lane >> 2;
            *(uint32_t*)(smem_raw + POFF_B + islice * PPITCH + (r0 * VMS + jcol) * 2)
                = packbf2(e0, e1);
            *(uint32_t*)(smem_raw + POFF_B + islice * PPITCH + ((r0 + 8) * VMS + jcol) * 2)
                = packbf2(e2, e3);
        }
        BAR_SYNC(1 + islice, 64);

        // ---- O += P V^T : warp 16i x 64c (its c-half), k=64 ----
        #pragma unroll
        for (int ks = 0; ks < 4; ks++) {
            uint32_t pfk[4];
            ldm_x4(pfk, sPa + (uint32_t)((rrow * VMS + ks * 16 + chalf) * 2));
            #pragma unroll
            for (int cg = 0; cg < 4; cg++) {
                uint32_t vb4[4];
                ldm_x4(vb4, vb + (uint32_t)(((half * 64 + cg * 16 + rrow) * VMS
                                             + ks * 16 + chalf) * 2));
                #pragma unroll
                for (int np = 0; np < 2; np++) {
                    uint32_t bb[2] = { vb4[np], vb4[np + 2] };
                    mma_bf16(accO[cg * 2 + np], pfk, bb);
                }
            }
        }
    }

    // ---- epilogue ----
    l0 += __shfl_xor_sync(0xFFFFFFFFu, l0, 1);
    l0 += __shfl_xor_sync(0xFFFFFFFFu, l0, 2);
    l1 += __shfl_xor_sync(0xFFFFFFFFu, l1, 1);
    l1 += __shfl_xor_sync(0xFFFFFFFFu, l1, 2);
    if ((lane & 3) == 0) {
        l_sm[half][islice * 16 + (lane >> 2)]     = l0;
        l_sm[half][islice * 16 + (lane >> 2) + 8] = l1;
    }
    __syncthreads();

    const int r = islice * 16 + (lane >> 2);
    const float il0 = 1.f / (l_sm[0][r] + l_sm[1][r]);
    const float il1 = 1.f / (l_sm[0][r + 8] + l_sm[1][r + 8]);
    const float g = *gamma;
    float* sO = (float*)smem_raw;

    #pragma unroll
    for (int t8 = 0; t8 < 8; t8++) {
        const int c = half * 64 + t8 * 8 + (lane & 3) * 2;
        const int i = islice * 16 + (lane >> 2);
        sO[(size_t)c * 68 + i]           = accO[t8][0] * il0;
        sO[(size_t)(c + 1) * 68 + i]     = accO[t8][1] * il0;
        sO[(size_t)c * 68 + i + 8]       = accO[t8][2] * il1;
        sO[(size_t)(c + 1) * 68 + i + 8] = accO[t8][3] * il1;
    }
    __syncthreads();
    #pragma unroll
    for (int rep = 0; rep < 8; rep++) {
        const int idx = rep * 256 + tid;
        const int c = idx >> 4, i4 = (idx & 15) * 4;
        const size_t base = ((size_t)b * C_ + c0 + c) * N_ + i0 + i4;
        const float4 xv = *(const float4*)(x + base);
        const float4 ov = *(const float4*)&sO[(size_t)c * 68 + i4];
        float4 o;
        o.x = g * ov.x + xv.x; o.y = g * ov.y + xv.y;
        o.z = g * ov.z + xv.z; o.w = g * ov.w + xv.w;
        *(float4*)(out + base) = o;
    }
}

// ---------------------------------------------------------------------------
// Launch
// ---------------------------------------------------------------------------
extern "C" void kernel_launch(void* const* d_in, const int* in_sizes, int n_in,
                              void* d_out, int out_size)
{
    const float* x     = (const float*)d_in[0];
    const float* wq    = (const float*)d_in[1];
    const float* bq    = (const float*)d_in[2];
    const float* wk    = (const float*)d_in[3];
    const float* bk    = (const float*)d_in[4];
    const float* wv    = (const float*)d_in[5];
    const float* bv    = (const float*)d_in[6];
    const float* gamma = (const float*)d_in[7];
    float* out = (float*)d_out;

    __nv_bfloat16 *pxt, *pqt, *pkt, *pvbf, *pwvbf;
    cudaGetSymbolAddress((void**)&pxt,   g_xt);
    cudaGetSymbolAddress((void**)&pqt,   g_qt);
    cudaGetSymbolAddress((void**)&pkt,   g_kt);
    cudaGetSymbolAddress((void**)&pvbf,  g_vbf);
    cudaGetSymbolAddress((void**)&pwvbf, g_wvbf);

    static bool attr_set = false;
    if (!attr_set) {
        cudaFuncSetAttribute(flash_tc, cudaFuncAttributeMaxDynamicSharedMemorySize,
                             FL_SMEM);
        attr_set = true;
    }

    prep_kernel<<<PREP_TOTAL, 256>>>(x, wq, bq, wk, bk, wv, pxt, pwvbf, pqt, pkt);
    projv_tc<<<dim3(N_ / 128, C_ / 128, B_), 256>>>(pwvbf, bv, pxt, pvbf);
    flash_tc<<<dim3(C_ / 128, N_ / 64, B_), 256, FL_SMEM>>>(pqt, pkt, pvbf, x, gamma, out);
}

// round 11
// speedup vs baseline: 1.2096x; 1.2096x over previous
#include <cuda_runtime.h>
#include <cuda_bf16.h>
#include <cstdint>

#define B_  8
#define C_  256
#define N_  2048
#define D_  32
#define BJ  64
#define NT  (N_ / BJ)
#define LOG2E 1.4426950408889634f

// ---------------------------------------------------------------------------
// Device-global scratch (allocation-free)
// ---------------------------------------------------------------------------
__device__ __nv_bfloat16  g_xt [(size_t)B_ * N_ * C_];   // x^T  (B,N,C) bf16
__device__ __nv_bfloat16  g_qt [(size_t)B_ * N_ * D_];   // q^T  (B,N,D) bf16, scaled by log2e
__device__ __nv_bfloat16  g_kt [(size_t)B_ * N_ * D_];   // k^T  (B,N,D) bf16
__device__ __nv_bfloat16  g_vbf[(size_t)B_ * C_ * N_];   // v    (B,C,N) bf16
__device__ __nv_bfloat16  g_wall[320 * C_];              // {wv; wq*log2e; wk} bf16
__device__ float          g_ball[320];                   // {bv; bq*log2e; bk}

// ---------------------------------------------------------------------------
// PTX helpers (legacy mma path: compute_100 PTX target)
// ---------------------------------------------------------------------------
__device__ __forceinline__ uint32_t smem_u32(const void* p) {
    uint32_t a;
    asm("{ .reg .u64 t; cvta.to.shared.u64 t, %1; cvt.u32.u64 %0, t; }"
        : "=r"(a) : "l"(p));
    return a;
}
__device__ __forceinline__ void ldm_x4(uint32_t* r, uint32_t addr) {
    asm volatile("ldmatrix.sync.aligned.m8n8.x4.shared.b16 {%0,%1,%2,%3}, [%4];\n"
        : "=r"(r[0]), "=r"(r[1]), "=r"(r[2]), "=r"(r[3]) : "r"(addr));
}
__device__ __forceinline__ void mma_bf16(float* d, const uint32_t* a, const uint32_t* b) {
    asm volatile(
        "mma.sync.aligned.m16n8k16.row.col.f32.bf16.bf16.f32 "
        "{%0,%1,%2,%3},{%4,%5,%6,%7},{%8,%9},{%0,%1,%2,%3};\n"
        : "+f"(d[0]), "+f"(d[1]), "+f"(d[2]), "+f"(d[3])
        : "r"(a[0]), "r"(a[1]), "r"(a[2]), "r"(a[3]), "r"(b[0]), "r"(b[1]));
}
__device__ __forceinline__ uint32_t packbf2(float a, float b) {
    __nv_bfloat162 h = __floats2bfloat162_rn(a, b);
    return *(uint32_t*)&h;
}
__device__ __forceinline__ float ex2(float x) {
    float y;
    asm("ex2.approx.f32 %0, %1;" : "=f"(y) : "f"(x));
    return y;
}
#define CP_ASYNC16(saddr, gptr) \
    asm volatile("cp.async.cg.shared.global [%0], [%1], 16;\n" :: "r"(saddr), "l"(gptr))
#define CP_COMMIT() asm volatile("cp.async.commit_group;\n")
#define CP_WAIT0()  asm volatile("cp.async.wait_group 0;\n")
#define CP_WAIT1()  asm volatile("cp.async.wait_group 1;\n")
#define BAR_SYNC(id, cnt) \
    asm volatile("bar.sync %0, %1;" :: "r"(id), "r"(cnt) : "memory")

#define SMS 40   // 32 data + 8 pad bf16
#define VMS 72   // 64 data + 8 pad bf16

// prep dispatch: pack_x 4096 | pack_wall 80 | bias 1
#define PREP_PACKX  4096
#define PREP_PACKW  (PREP_PACKX + 80)
#define PREP_TOTAL  (PREP_PACKW + 1)

// ---------------------------------------------------------------------------
// prep: pack_x (transpose+bf16), pack_wall (wv|wq*log2e|wk), biases
// ---------------------------------------------------------------------------
__global__ __launch_bounds__(256) void prep_kernel(
    const float* __restrict__ x,
    const float* __restrict__ wq, const float* __restrict__ bq,
    const float* __restrict__ wk, const float* __restrict__ bk,
    const float* __restrict__ wv, const float* __restrict__ bv,
    __nv_bfloat16* __restrict__ xt, __nv_bfloat16* __restrict__ wall,
    float* __restrict__ ball)
{
    __shared__ float t[32][33];
    const int bid = blockIdx.x, tid = threadIdx.x;

    if (bid < PREP_PACKX) {
        // ---- pack_x: 64 n-tiles x 8 c-tiles x 8 b ----
        const int n0 = (bid & 63) * 32, c0 = ((bid >> 6) & 7) * 32, b = bid >> 9;
        #pragma unroll
        for (int r = 0; r < 4; r++) {
            const int c = (tid >> 5) + r * 8;
            t[c][tid & 31] = x[((size_t)b * C_ + c0 + c) * N_ + n0 + (tid & 31)];
        }
        __syncthreads();
        #pragma unroll
        for (int r = 0; r < 4; r++) {
            const int n = (tid >> 5) + r * 8;
            xt[((size_t)b * N_ + n0 + n) * C_ + c0 + (tid & 31)] =
                __float2bfloat16(t[tid & 31][n]);
        }
        return;
    }
    if (bid < PREP_PACKW) {
        // ---- pack_wall: blocks 0-63 wv, 64-71 wq*log2e, 72-79 wk ----
        const int blk = bid - PREP_PACKX;
        const float* src = (blk < 64) ? (wv + blk * 1024)
                         : (blk < 72) ? (wq + (blk - 64) * 1024)
                                      : (wk + (blk - 72) * 1024);
        const float scl = (blk >= 64 && blk < 72) ? LOG2E : 1.0f;
        const int off = tid * 4;
        const float4 w4 = *(const float4*)(src + off);
        __nv_bfloat16* dst = wall + blk * 1024 + off;
        *(__nv_bfloat162*)(dst)     = __floats2bfloat162_rn(w4.x * scl, w4.y * scl);
        *(__nv_bfloat162*)(dst + 2) = __floats2bfloat162_rn(w4.z * scl, w4.w * scl);
        return;
    }
    // ---- biases ----
    if (tid < 256) ball[tid] = bv[tid];
    if (tid < 32) {
        ball[256 + tid] = bq[tid] * LOG2E;
        ball[288 + tid] = bk[tid];
    }
}

// ---------------------------------------------------------------------------
// projall: [320 x 2048 x 256] bf16 GEMM per batch.
//   rows 0-255  -> v  (B,C,N) + bv
//   rows 256-287-> q^T (B,N,32) (weights/bias pre-scaled by log2e)
//   rows 288-319-> k^T (B,N,32)
// BM=64, BN=128, BK=32. 8 warps = 4 m-slices x 2 n-halves, 16x64 warp tile.
// grid (16, 5, 8) = 640 blocks.
// ---------------------------------------------------------------------------
__global__ __launch_bounds__(256) void projall_tc(
    const __nv_bfloat16* __restrict__ wall, const float* __restrict__ ball,
    const __nv_bfloat16* __restrict__ xt,
    __nv_bfloat16* __restrict__ v, __nv_bfloat16* __restrict__ qt,
    __nv_bfloat16* __restrict__ kt)
{
    __shared__ __align__(16) __nv_bfloat16 sm[2 * 64 * SMS + 2 * 128 * SMS];
    const int b = blockIdx.z, m0 = blockIdx.y * 64, n0 = blockIdx.x * 128;
    const int tid = threadIdx.x, lane = tid & 31, warp = tid >> 5;
    const int islice = warp >> 1, half = warp & 1;
    const int rrow = lane & 15, chalf = (lane >> 4) << 3;
    const uint32_t sAb = smem_u32(sm);
    const uint32_t sBb = sAb + 2 * 64 * SMS * 2;

    const int arow = tid >> 2, c8 = (tid & 3) * 8;
    const __nv_bfloat16* A  = wall + (size_t)(m0 + arow) * C_ + c8;

    float acc[8][4] = {};

    // prefetch chunk 0
    {
        CP_ASYNC16(sAb + (uint32_t)((arow * SMS + c8) * 2), A);
        #pragma unroll
        for (int p = 0; p < 2; p++) {
            const int idx = tid + p * 256, br = idx >> 2, bs = (idx & 3) * 8;
            CP_ASYNC16(sBb + (uint32_t)((br * SMS + bs) * 2),
                       xt + ((size_t)b * N_ + n0 + br) * C_ + bs);
        }
        CP_COMMIT();
    }
    #pragma unroll 1
    for (int it = 0; it < 8; it++) {
        CP_WAIT0(); __syncthreads();
        if (it < 7) {
            const int st = (it + 1) & 1, j0 = (it + 1) * 32;
            CP_ASYNC16(sAb + (uint32_t)((st * 64 * SMS + arow * SMS + c8) * 2), A + j0);
            #pragma unroll
            for (int p = 0; p < 2; p++) {
                const int idx = tid + p * 256, br = idx >> 2, bs = (idx & 3) * 8;
                CP_ASYNC16(sBb + (uint32_t)((st * 128 * SMS + br * SMS + bs) * 2),
                           xt + ((size_t)b * N_ + n0 + br) * C_ + j0 + bs);
            }
            CP_COMMIT();
        }
        const uint32_t sA = sAb + (uint32_t)((it & 1) * 64 * SMS * 2);
        const uint32_t sB = sBb + (uint32_t)((it & 1) * 128 * SMS * 2);
        #pragma unroll
        for (int ks2 = 0; ks2 < 2; ks2++) {
            const int ks = ks2 * 16;
            uint32_t af[4];
            ldm_x4(af, sA + (uint32_t)(((islice * 16 + rrow) * SMS + ks + chalf) * 2));
            #pragma unroll
            for (int cg = 0; cg < 4; cg++) {
                uint32_t bf4[4];
                ldm_x4(bf4, sB + (uint32_t)(((half * 64 + cg * 16 + rrow) * SMS
                                             + ks + chalf) * 2));
                #pragma unroll
                for (int np = 0; np < 2; np++) {
                    uint32_t bb[2] = { bf4[np], bf4[np + 2] };
                    mma_bf16(acc[cg * 2 + np], af, bb);
                }
            }
        }
        __syncthreads();
    }

    // ---- epilogue: route by m-tile ----
    const int mrow = m0 + islice * 16 + (lane >> 2);
    const float bl0 = ball[mrow], bl8 = ball[mrow + 8];
    #pragma unroll
    for (int t8 = 0; t8 < 8; t8++) {
        const int n = n0 + half * 64 + t8 * 8 + (lane & 3) * 2;
        const float v0 = acc[t8][0] + bl0, v1 = acc[t8][1] + bl0;
        const float v2 = acc[t8][2] + bl8, v3 = acc[t8][3] + bl8;
        if (m0 < 256) {
            *(__nv_bfloat162*)(v + ((size_t)b * C_ + mrow) * N_ + n) =
                __floats2bfloat162_rn(v0, v1);
            *(__nv_bfloat162*)(v + ((size_t)b * C_ + mrow + 8) * N_ + n) =
                __floats2bfloat162_rn(v2, v3);
        } else {
            // islice 0,1 -> q rows 0..31; islice 2,3 -> k rows 0..31 (warp-uniform)
            const int mq = mrow - 256;
            __nv_bfloat16* dst = (mq < 32) ? qt : kt;
            const int md = mq & 31;
            dst[((size_t)b * N_ + n) * D_ + md]         = __float2bfloat16(v0);
            dst[((size_t)b * N_ + n + 1) * D_ + md]     = __float2bfloat16(v1);
            dst[((size_t)b * N_ + n) * D_ + md + 8]     = __float2bfloat16(v2);
            dst[((size_t)b * N_ + n + 1) * D_ + md + 8] = __float2bfloat16(v3);
        }
    }
}

// ---------------------------------------------------------------------------
// Flash attention (base-2 softmax, no max; q pre-scaled by log2e).
// Block = 64 i-rows x 128 c, 8 warps = 4 i-slices x 2 halves.
// ---------------------------------------------------------------------------
#define KOFF_B  (64 * SMS * 2)
#define VOFF_B  (KOFF_B + 3 * 64 * SMS * 2)
#define POFF_B  (VOFF_B + 3 * 128 * VMS * 2)
#define PPITCH  (16 * VMS * 2)
#define FL_SMEM (POFF_B + 4 * PPITCH)   // 84992

__global__ __launch_bounds__(256, 2) void flash_tc(
    const __nv_bfloat16* __restrict__ qt, const __nv_bfloat16* __restrict__ kt,
    const __nv_bfloat16* __restrict__ v, const float* __restrict__ x,
    const float* __restrict__ gamma, float* __restrict__ out)
{
    extern __shared__ __align__(16) char smem_raw[];
    __shared__ float l_sm[2][64];

    const int b  = blockIdx.z;
    const int i0 = blockIdx.y * 64;
    const int c0 = blockIdx.x * 128;
    const int tid = threadIdx.x, lane = tid & 31, warp = tid >> 5;
    const int islice = warp >> 1;
    const int half   = warp & 1;
    const int rrow = lane & 15, chalf = (lane >> 4) << 3;

    const __nv_bfloat16* Qg = qt + ((size_t)b * N_ + i0) * D_;
    const __nv_bfloat16* Kg = kt + (size_t)b * N_ * D_;
    const __nv_bfloat16* Vg = v  + ((size_t)b * C_ + c0) * N_;

    const uint32_t sQa = smem_u32(smem_raw);
    const uint32_t sKa = sQa + KOFF_B;
    const uint32_t sVa = sQa + VOFF_B;
    const uint32_t sPa = sQa + POFF_B + (uint32_t)islice * PPITCH;

    {
        const int r = tid >> 2, s = (tid & 3) * 8;
        CP_ASYNC16(sQa + (uint32_t)((r * SMS + s) * 2), Qg + (size_t)r * D_ + s);
        CP_ASYNC16(sKa + (uint32_t)((r * SMS + s) * 2), Kg + (size_t)r * D_ + s);
        #pragma unroll
        for (int p = 0; p < 4; p++) {
            const int idx = tid + p * 256, vr = idx >> 3, vs = (idx & 7) * 8;
            CP_ASYNC16(sVa + (uint32_t)((vr * VMS + vs) * 2), Vg + (size_t)vr * N_ + vs);
        }
        CP_COMMIT();
        CP_ASYNC16(sKa + (uint32_t)((64 * SMS + r * SMS + s) * 2),
                   Kg + (size_t)(BJ + r) * D_ + s);
        #pragma unroll
        for (int p = 0; p < 4; p++) {
            const int idx = tid + p * 256, vr = idx >> 3, vs = (idx & 7) * 8;
            CP_ASYNC16(sVa + (uint32_t)((128 * VMS + vr * VMS + vs) * 2),
                       Vg + (size_t)vr * N_ + BJ + vs);
        }
        CP_COMMIT();
    }

    float accO[8][4] = {};
    float l0 = 0.f, l1 = 0.f;
    uint32_t qf[2][4];

    #pragma unroll 1
    for (int t = 0; t < NT; t++) {
        CP_WAIT1(); __syncthreads();
        if (t == 0) {
            ldm_x4(qf[0], sQa + (uint32_t)(((islice * 16 + rrow) * SMS + 0  + chalf) * 2));
            ldm_x4(qf[1], sQa + (uint32_t)(((islice * 16 + rrow) * SMS + 16 + chalf) * 2));
        }
        if (t + 2 < NT) {
            const int bf = (t + 2) % 3, j1 = (t + 2) * BJ;
            const int r = tid >> 2, s = (tid & 3) * 8;
            CP_ASYNC16(sKa + (uint32_t)((bf * 64 * SMS + r * SMS + s) * 2),
                       Kg + (size_t)(j1 + r) * D_ + s);
            #pragma unroll
            for (int p = 0; p < 4; p++) {
                const int idx = tid + p * 256, vr = idx >> 3, vs = (idx & 7) * 8;
                CP_ASYNC16(sVa + (uint32_t)((bf * 128 * VMS + vr * VMS + vs) * 2),
                           Vg + (size_t)vr * N_ + j1 + vs);
            }
        }
        CP_COMMIT();

        const uint32_t kb = sKa + (uint32_t)((t % 3) * 64 * SMS * 2);
        const uint32_t vb = sVa + (uint32_t)((t % 3) * 128 * VMS * 2);

        float accS[4][4] = {};
        #pragma unroll
        for (int jt2 = 0; jt2 < 2; jt2++) {
            const int jt = half * 2 + jt2;
            uint32_t b0[4], b1[4];
            ldm_x4(b0, kb + (uint32_t)(((jt * 16 + rrow) * SMS + 0  + chalf) * 2));
            ldm_x4(b1, kb + (uint32_t)(((jt * 16 + rrow) * SMS + 16 + chalf) * 2));
            #pragma unroll
            for (int np = 0; np < 2; np++) {
                uint32_t bb0[2] = { b0[np], b0[np + 2] };
                uint32_t bb1[2] = { b1[np], b1[np + 2] };
                mma_bf16(accS[jt2 * 2 + np], qf[0], bb0);
                mma_bf16(accS[jt2 * 2 + np], qf[1], bb1);
            }
        }

        #pragma unroll
        for (int t4 = 0; t4 < 4; t4++) {
            const float e0 = ex2(accS[t4][0]);
            const float e1 = ex2(accS[t4][1]);
            const float e2 = ex2(accS[t4][2]);
            const float e3 = ex2(accS[t4][3]);
            l0 += e0 + e1; l1 += e2 + e3;
            const int jcol = half * 32 + t4 * 8 + (lane & 3) * 2;
            const int r0 = lane >> 2;
            *(uint32_t*)(smem_raw + POFF_B + islice * PPITCH + (r0 * VMS + jcol) * 2)
                = packbf2(e0, e1);
            *(uint32_t*)(smem_raw + POFF_B + islice * PPITCH + ((r0 + 8) * VMS + jcol) * 2)
                = packbf2(e2, e3);
        }
        BAR_SYNC(1 + islice, 64);

        #pragma unroll
        for (int ks = 0; ks < 4; ks++) {
            uint32_t pfk[4];
            ldm_x4(pfk, sPa + (uint32_t)((rrow * VMS + ks * 16 + chalf) * 2));
            #pragma unroll
            for (int cg = 0; cg < 4; cg++) {
                uint32_t vb4[4];
                ldm_x4(vb4, vb + (uint32_t)(((half * 64 + cg * 16 + rrow) * VMS
                                             + ks * 16 + chalf) * 2));
                #pragma unroll
                for (int np = 0; np < 2; np++) {
                    uint32_t bb[2] = { vb4[np], vb4[np + 2] };
                    mma_bf16(accO[cg * 2 + np], pfk, bb);
                }
            }
        }
    }

    // ---- epilogue ----
    l0 += __shfl_xor_sync(0xFFFFFFFFu, l0, 1);
    l0 += __shfl_xor_sync(0xFFFFFFFFu, l0, 2);
    l1 += __shfl_xor_sync(0xFFFFFFFFu, l1, 1);
    l1 += __shfl_xor_sync(0xFFFFFFFFu, l1, 2);
    if ((lane & 3) == 0) {
        l_sm[half][islice * 16 + (lane >> 2)]     = l0;
        l_sm[half][islice * 16 + (lane >> 2) + 8] = l1;
    }
    __syncthreads();

    const int r = islice * 16 + (lane >> 2);
    const float il0 = 1.f / (l_sm[0][r] + l_sm[1][r]);
    const float il1 = 1.f / (l_sm[0][r + 8] + l_sm[1][r + 8]);
    const float g = *gamma;
    float* sO = (float*)smem_raw;

    #pragma unroll
    for (int t8 = 0; t8 < 8; t8++) {
        const int c = half * 64 + t8 * 8 + (lane & 3) * 2;
        const int i = islice * 16 + (lane >> 2);
        sO[(size_t)c * 68 + i]           = accO[t8][0] * il0;
        sO[(size_t)(c + 1) * 68 + i]     = accO[t8][1] * il0;
        sO[(size_t)c * 68 + i + 8]       = accO[t8][2] * il1;
        sO[(size_t)(c + 1) * 68 + i + 8] = accO[t8][3] * il1;
    }
    __syncthreads();
    #pragma unroll
    for (int rep = 0; rep < 8; rep++) {
        const int idx = rep * 256 + tid;
        const int c = idx >> 4, i4 = (idx & 15) * 4;
        const size_t base = ((size_t)b * C_ + c0 + c) * N_ + i0 + i4;
        const float4 xv = *(const float4*)(x + base);
        const float4 ov = *(const float4*)&sO[(size_t)c * 68 + i4];
        float4 o;
        o.x = g * ov.x + xv.x; o.y = g * ov.y + xv.y;
        o.z = g * ov.z + xv.z; o.w = g * ov.w + xv.w;
        *(float4*)(out + base) = o;
    }
}

// ---------------------------------------------------------------------------
// Launch
// ---------------------------------------------------------------------------
extern "C" void kernel_launch(void* const* d_in, const int* in_sizes, int n_in,
                              void* d_out, int out_size)
{
    const float* x     = (const float*)d_in[0];
    const float* wq    = (const float*)d_in[1];
    const float* bq    = (const float*)d_in[2];
    const float* wk    = (const float*)d_in[3];
    const float* bk    = (const float*)d_in[4];
    const float* wv    = (const float*)d_in[5];
    const float* bv    = (const float*)d_in[6];
    const float* gamma = (const float*)d_in[7];
    float* out = (float*)d_out;

    __nv_bfloat16 *pxt, *pqt, *pkt, *pvbf, *pwall;
    float* pball;
    cudaGetSymbolAddress((void**)&pxt,   g_xt);
    cudaGetSymbolAddress((void**)&pqt,   g_qt);
    cudaGetSymbolAddress((void**)&pkt,   g_kt);
    cudaGetSymbolAddress((void**)&pvbf,  g_vbf);
    cudaGetSymbolAddress((void**)&pwall, g_wall);
    cudaGetSymbolAddress((void**)&pball, g_ball);

    static bool attr_set = false;
    if (!attr_set) {
        cudaFuncSetAttribute(flash_tc, cudaFuncAttributeMaxDynamicSharedMemorySize,
                             FL_SMEM);
        attr_set = true;
    }

    prep_kernel<<<PREP_TOTAL, 256>>>(x, wq, bq, wk, bk, wv, bv, pxt, pwall, pball);
    projall_tc<<<dim3(N_ / 128, 5, B_), 256>>>(pwall, pball, pxt, pvbf, pqt, pkt);
    flash_tc<<<dim3(C_ / 128, N_ / 64, B_), 256, FL_SMEM>>>(pqt, pkt, pvbf, x, gamma, out);
}